// round 1
// baseline (speedup 1.0000x reference)
#include <cuda_runtime.h>

// Problem constants (from reference)
#define SEQ    4096
#define CIN    7
#define NK     586        // 585 regular kernels + 1 "last"
#define GLEN   12288      // SEQ * KW(3)
#define HP     12289      // output positions per channel-kernel row
#define GPITCH 12304      // GLEN + 16 (4 left pad + >=3 right pad + slack), 16B-aligned rows
#define CTOT   4096       // 7*585 + 1
#define HTILE  32

// Scratch (allocation-free rule: __device__ globals)
__device__ float g_Gpad[CIN * GPITCH];   // padded gathered signals, Gpad[ch][h] = g_ch[h-4] (0 outside)
__device__ float g_Wmid[NK * 8];         // middle column of each 8x3 kernel

// ---- prep kernel 1: extract middle kernel column ----
__global__ void prep_w(const float* __restrict__ kernels) {
    int idx = blockIdx.x * blockDim.x + threadIdx.x;
    if (idx < NK * 8) {
        int k = idx >> 3, a = idx & 7;
        g_Wmid[idx] = kernels[k * 24 + a * 3 + 1];
    }
}

// ---- prep kernel 2: build padded gathered signal ----
__global__ void prep_g(const float* __restrict__ x) {
    int idx = blockIdx.x * blockDim.x + threadIdx.x;
    if (idx < CIN * GPITCH) {
        int ch = idx / GPITCH;
        int i  = idx - ch * GPITCH;
        int t  = i - 4;                      // signal index with left pad of 4
        float v = 0.f;
        if (t >= 0 && t < GLEN) {
            int s = t / 3;
            int j = t - s * 3;
            int src = s + j;
            if (src > SEQ - 1) src = SEQ - 1;
            v = x[src * CIN + ch];           // x layout: (1, SEQ, CIN, 1) row-major
        }
        g_Gpad[idx] = v;
    }
}

// ---- main kernel: each thread computes 4 consecutive c for HTILE h values ----
__global__ void __launch_bounds__(256) conv_main(float* __restrict__ out) {
    const int tid = threadIdx.x;
    const int c0  = (blockIdx.x * 256 + tid) * 4;    // gridDim.x = 4 -> c0 in [0,4096)
    const int h0  = blockIdx.y * HTILE;

    int ch[4], kk[4];
#pragma unroll
    for (int j = 0; j < 4; j++) {
        int c = c0 + j;
        if (c < CTOT - 1) { ch[j] = c / 585; kk[j] = c - ch[j] * 585; }
        else              { ch[j] = 0;       kk[j] = 585; }
    }

    // load 8-tap weights for each of the 4 outputs (contiguous float4 pairs)
    float w[4][8];
#pragma unroll
    for (int j = 0; j < 4; j++) {
        float4 lo = *(const float4*)&g_Wmid[kk[j] * 8];
        float4 hi = *(const float4*)&g_Wmid[kk[j] * 8 + 4];
        w[j][0] = lo.x; w[j][1] = lo.y; w[j][2] = lo.z; w[j][3] = lo.w;
        w[j][4] = hi.x; w[j][5] = hi.y; w[j][6] = hi.z; w[j][7] = hi.w;
    }

    const bool uniform = (ch[0] == ch[1]) && (ch[1] == ch[2]) && (ch[2] == ch[3]);
    const bool fulltile = (h0 + HTILE <= HP);

    if (uniform && fulltile) {
        // Fast path: one shared sliding window of g for all 4 outputs.
        const float* __restrict__ gp = &g_Gpad[ch[0] * GPITCH + h0];
        float r[16];
        {
            float4 a0 = *(const float4*)&gp[0];
            float4 a1 = *(const float4*)&gp[4];
            r[0]=a0.x; r[1]=a0.y; r[2]=a0.z; r[3]=a0.w;
            r[4]=a1.x; r[5]=a1.y; r[6]=a1.z; r[7]=a1.w;
        }
#pragma unroll
        for (int hb = 0; hb < HTILE; hb += 8) {
            // prefetch next 8 window values (in-bounds thanks to GPITCH slack)
            float4 n0 = *(const float4*)&gp[hb + 8];
            float4 n1 = *(const float4*)&gp[hb + 12];
            r[8]=n0.x;  r[9]=n0.y;  r[10]=n0.z; r[11]=n0.w;
            r[12]=n1.x; r[13]=n1.y; r[14]=n1.z; r[15]=n1.w;
#pragma unroll
            for (int u = 0; u < 8; u++) {
                float a0 = 0.f, a1 = 0.f, a2 = 0.f, a3 = 0.f;
#pragma unroll
                for (int a = 0; a < 8; a++) {
                    float gv = r[u + a];
                    a0 = fmaf(gv, w[0][a], a0);
                    a1 = fmaf(gv, w[1][a], a1);
                    a2 = fmaf(gv, w[2][a], a2);
                    a3 = fmaf(gv, w[3][a], a3);
                }
                float4 o; o.x = a0; o.y = a1; o.z = a2; o.w = a3;
                *(float4*)&out[(size_t)(h0 + hb + u) * CTOT + c0] = o;
            }
#pragma unroll
            for (int a = 0; a < 8; a++) r[a] = r[8 + a];
        }
    } else {
        // Slow path: channel-boundary groups (6 threads total) and the 1-row tail tile.
        int hEnd = min(h0 + HTILE, HP);
        for (int h = h0; h < hEnd; h++) {
            float acc[4];
#pragma unroll
            for (int j = 0; j < 4; j++) {
                const float* gp = &g_Gpad[ch[j] * GPITCH + h];
                float s = 0.f;
#pragma unroll
                for (int a = 0; a < 8; a++) s = fmaf(gp[a], w[j][a], s);
                acc[j] = s;
            }
            float4 o; o.x = acc[0]; o.y = acc[1]; o.z = acc[2]; o.w = acc[3];
            *(float4*)&out[(size_t)h * CTOT + c0] = o;
        }
    }
}

extern "C" void kernel_launch(void* const* d_in, const int* in_sizes, int n_in,
                              void* d_out, int out_size) {
    // Identify inputs defensively by element count: x=28672, kernels=14064
    const float* x       = (const float*)d_in[0];
    const float* kernels = (const float*)d_in[1];
    if (n_in >= 2 && in_sizes[0] == NK * 24) {   // swapped order
        kernels = (const float*)d_in[0];
        x       = (const float*)d_in[1];
    }
    float* out = (float*)d_out;

    prep_w<<<(NK * 8 + 255) / 256, 256>>>(kernels);
    prep_g<<<(CIN * GPITCH + 255) / 256, 256>>>(x);

    dim3 grid(CTOT / (256 * 4), (HP + HTILE - 1) / HTILE);  // (4, 385)
    conv_main<<<grid, 256>>>(out);
}

// round 2
// speedup vs baseline: 1.0927x; 1.0927x over previous
#include <cuda_runtime.h>

// Problem constants (from reference)
#define SEQ    4096
#define CIN    7
#define NK     586        // 585 regular kernels + 1 "last"
#define GLEN   12288      // SEQ * KW(3)
#define HP     12289      // output positions per channel-kernel row
#define GPITCH 12304      // GLEN + 16 (4 left pad + >=3 right pad + slack)
#define CTOT   4096       // 7*585 + 1
#define HTILE  32

// Scratch (allocation-free rule: __device__ globals)
__device__ float g_Gpad[CIN * GPITCH];   // Gpad[ch][i] = g_ch[i-4] (0 outside)
__device__ float g_Wmid[NK * 8];         // middle column of each 8x3 kernel

// ---- packed f32x2 helpers (Blackwell sm_103a) ----
typedef unsigned long long u64;
__device__ __forceinline__ u64 pk2(float lo, float hi) {
    u64 r; asm("mov.b64 %0, {%1,%2};" : "=l"(r) : "f"(lo), "f"(hi)); return r;
}
__device__ __forceinline__ void upk2(float& lo, float& hi, u64 v) {
    asm("mov.b64 {%0,%1}, %2;" : "=f"(lo), "=f"(hi) : "l"(v));
}
__device__ __forceinline__ u64 fma2(u64 a, u64 b, u64 c) {
    u64 d; asm("fma.rn.f32x2 %0, %1, %2, %3;" : "=l"(d) : "l"(a), "l"(b), "l"(c)); return d;
}

// ---- fused prep kernel: weights mid-column + padded gathered signal ----
__global__ void prep(const float* __restrict__ x, const float* __restrict__ kernels) {
    int idx = blockIdx.x * blockDim.x + threadIdx.x;
    if (idx < NK * 8) {
        int k = idx >> 3, a = idx & 7;
        g_Wmid[idx] = kernels[k * 24 + a * 3 + 1];
    }
    if (idx < CIN * GPITCH) {
        int ch = idx / GPITCH;
        int i  = idx - ch * GPITCH;
        int t  = i - 4;
        float v = 0.f;
        if (t >= 0 && t < GLEN) {
            int s = t / 3;
            int j = t - s * 3;
            int src = s + j;
            if (src > SEQ - 1) src = SEQ - 1;
            v = x[src * CIN + ch];
        }
        g_Gpad[idx] = v;
    }
}

// ---- main kernel: 4 consecutive c per thread, HTILE h rows, f32x2 over h-pairs ----
__global__ void __launch_bounds__(256) conv_main(float* __restrict__ out) {
    const int tid = threadIdx.x;
    const int c0  = (blockIdx.x * 256 + tid) * 4;    // gridDim.x = 4
    const int h0  = blockIdx.y * HTILE;

    int ch[4], kk[4];
#pragma unroll
    for (int j = 0; j < 4; j++) {
        int c = c0 + j;
        if (c < CTOT - 1) { ch[j] = c / 585; kk[j] = c - ch[j] * 585; }
        else              { ch[j] = 0;       kk[j] = 585; }
    }

    // Load 8-tap weights for the 4 outputs
    float w[4][8];
#pragma unroll
    for (int j = 0; j < 4; j++) {
        float4 lo = *(const float4*)&g_Wmid[kk[j] * 8];
        float4 hi = *(const float4*)&g_Wmid[kk[j] * 8 + 4];
        w[j][0] = lo.x; w[j][1] = lo.y; w[j][2] = lo.z; w[j][3] = lo.w;
        w[j][4] = hi.x; w[j][5] = hi.y; w[j][6] = hi.z; w[j][7] = hi.w;
    }

    const bool uniform  = (ch[0] == ch[1]) && (ch[1] == ch[2]) && (ch[2] == ch[3]);
    const bool fulltile = (h0 + HTILE <= HP);

    if (uniform && fulltile) {
        // Pre-pack weights as (w,w) for lanewise f32x2 FMA
        u64 W2[4][8];
#pragma unroll
        for (int j = 0; j < 4; j++)
#pragma unroll
            for (int a = 0; a < 8; a++) W2[j][a] = pk2(w[j][a], w[j][a]);

        const float* __restrict__ gp = &g_Gpad[ch[0] * GPITCH + h0];
        float r[16];
        {
            float4 a0 = *(const float4*)&gp[0];
            float4 a1 = *(const float4*)&gp[4];
            r[0]=a0.x; r[1]=a0.y; r[2]=a0.z; r[3]=a0.w;
            r[4]=a1.x; r[5]=a1.y; r[6]=a1.z; r[7]=a1.w;
        }
#pragma unroll
        for (int hb = 0; hb < HTILE; hb += 8) {
            float4 n0 = *(const float4*)&gp[hb + 8];
            float4 n1 = *(const float4*)&gp[hb + 12];
            r[8]=n0.x;  r[9]=n0.y;  r[10]=n0.z; r[11]=n0.w;
            r[12]=n1.x; r[13]=n1.y; r[14]=n1.z; r[15]=n1.w;

            // g-pairs at offsets 0..13 (shared across all 4 outputs and u-pairs)
            u64 P[14];
#pragma unroll
            for (int o = 0; o < 14; o++) P[o] = pk2(r[o], r[o + 1]);

#pragma unroll
            for (int up = 0; up < 8; up += 2) {
                u64 acc0 = 0ull, acc1 = 0ull, acc2 = 0ull, acc3 = 0ull;
#pragma unroll
                for (int a = 0; a < 8; a++) {
                    u64 gpair = P[up + a];
                    acc0 = fma2(gpair, W2[0][a], acc0);
                    acc1 = fma2(gpair, W2[1][a], acc1);
                    acc2 = fma2(gpair, W2[2][a], acc2);
                    acc3 = fma2(gpair, W2[3][a], acc3);
                }
                float o0u, o0v, o1u, o1v, o2u, o2v, o3u, o3v;
                upk2(o0u, o0v, acc0); upk2(o1u, o1v, acc1);
                upk2(o2u, o2v, acc2); upk2(o3u, o3v, acc3);
                float4 ru; ru.x=o0u; ru.y=o1u; ru.z=o2u; ru.w=o3u;
                float4 rv; rv.x=o0v; rv.y=o1v; rv.z=o2v; rv.w=o3v;
                *(float4*)&out[(size_t)(h0 + hb + up)     * CTOT + c0] = ru;
                *(float4*)&out[(size_t)(h0 + hb + up + 1) * CTOT + c0] = rv;
            }
#pragma unroll
            for (int a = 0; a < 8; a++) r[a] = r[8 + a];
        }
    } else {
        // Slow path: channel-boundary quads and the 1-row tail tile.
        int hEnd = min(h0 + HTILE, HP);
        for (int h = h0; h < hEnd; h++) {
            float acc[4];
#pragma unroll
            for (int j = 0; j < 4; j++) {
                const float* gp = &g_Gpad[ch[j] * GPITCH + h];
                float s = 0.f;
#pragma unroll
                for (int a = 0; a < 8; a++) s = fmaf(gp[a], w[j][a], s);
                acc[j] = s;
            }
            float4 o; o.x = acc[0]; o.y = acc[1]; o.z = acc[2]; o.w = acc[3];
            *(float4*)&out[(size_t)h * CTOT + c0] = o;
        }
    }
}

extern "C" void kernel_launch(void* const* d_in, const int* in_sizes, int n_in,
                              void* d_out, int out_size) {
    const float* x       = (const float*)d_in[0];
    const float* kernels = (const float*)d_in[1];
    if (n_in >= 2 && in_sizes[0] == NK * 24) {   // defensive: swapped order
        kernels = (const float*)d_in[0];
        x       = (const float*)d_in[1];
    }
    float* out = (float*)d_out;

    prep<<<(CIN * GPITCH + 255) / 256, 256>>>(x, kernels);

    dim3 grid(CTOT / (256 * 4), (HP + HTILE - 1) / HTILE);  // (4, 385)
    conv_main<<<grid, 256>>>(out);
}

// round 3
// speedup vs baseline: 1.7391x; 1.5916x over previous
#include <cuda_runtime.h>

// Problem constants (from reference)
#define SEQ    4096
#define CIN    7
#define NK     586        // 585 regular kernels + 1 "last"
#define GLEN   12288      // SEQ * KW(3)
#define HP     12289      // output positions per channel-kernel row
#define GPITCH 12304      // GLEN + 16 (4 left pad + right slack)
#define CTOT   4096       // 7*585 + 1
#define NCP    2048       // c-pairs
#define HTILE  32

// Scratch (allocation-free rule: __device__ globals)
__device__ float g_Gpad[CIN * GPITCH];           // Gpad[ch][i] = g_ch[i-4] (0 outside)
__device__ float g_Wmid[NK * 8];                 // middle column of each 8x3 kernel
__device__ unsigned long long g_Wpk[NCP * 8];    // packed (w_{2cp}[a], w_{2cp+1}[a])

typedef unsigned long long u64;
__device__ __forceinline__ u64 pk2(float lo, float hi) {
    u64 r; asm("mov.b64 %0, {%1,%2};" : "=l"(r) : "f"(lo), "f"(hi)); return r;
}
__device__ __forceinline__ u64 fma2(u64 a, u64 b, u64 c) {
    u64 d; asm("fma.rn.f32x2 %0, %1, %2, %3;" : "=l"(d) : "l"(a), "l"(b), "l"(c)); return d;
}

// ---- fused prep: mid-column weights, packed weight pairs, padded gathered signal ----
__global__ void prep(const float* __restrict__ x, const float* __restrict__ kernels) {
    int idx = blockIdx.x * blockDim.x + threadIdx.x;
    if (idx < NK * 8) {
        int k = idx >> 3, a = idx & 7;
        g_Wmid[idx] = kernels[k * 24 + a * 3 + 1];
    }
    if (idx < NCP * 8) {
        int cp = idx >> 3, a = idx & 7;
        int c0 = 2 * cp, c1 = c0 + 1;
        int k0 = (c0 == CTOT - 1) ? 585 : (c0 % 585);
        int k1 = (c1 == CTOT - 1) ? 585 : (c1 % 585);
        g_Wpk[idx] = pk2(kernels[k0 * 24 + a * 3 + 1], kernels[k1 * 24 + a * 3 + 1]);
    }
    if (idx < CIN * GPITCH) {
        int ch = idx / GPITCH;
        int i  = idx - ch * GPITCH;
        int t  = i - 4;
        float v = 0.f;
        if (t >= 0 && t < GLEN) {
            int s = t / 3;
            int j = t - s * 3;
            int src = s + j;
            if (src > SEQ - 1) src = SEQ - 1;
            v = x[src * CIN + ch];
        }
        g_Gpad[idx] = v;
    }
}

// ---- main kernel: one c-pair per thread, HTILE h rows, f32x2 over the c-pair ----
__global__ void __launch_bounds__(256, 4) conv_main(float* __restrict__ out) {
    const int tid = threadIdx.x;
    const int cp  = blockIdx.x * 256 + tid;          // [0, 2048), grid.x = 8
    const int c0  = cp * 2;
    const int h0  = blockIdx.y * HTILE;

    const int ch0 = c0 / 585;                        // c0 even -> never the special 4095
    const int c1  = c0 + 1;
    const int ch1 = (c1 == CTOT - 1) ? 0 : c1 / 585;

    const bool uniform  = (ch0 == ch1);
    const bool fulltile = (h0 + HTILE <= HP);

    if (uniform && fulltile) {
        // 8 packed weight pairs: (w_c0[a], w_c1[a])
        u64 Wp[8];
        {
            const ulonglong2* wq = (const ulonglong2*)&g_Wpk[cp * 8];
            ulonglong2 q0 = wq[0], q1 = wq[1], q2 = wq[2], q3 = wq[3];
            Wp[0] = q0.x; Wp[1] = q0.y; Wp[2] = q1.x; Wp[3] = q1.y;
            Wp[4] = q2.x; Wp[5] = q2.y; Wp[6] = q3.x; Wp[7] = q3.y;
        }

        const float* __restrict__ gp = &g_Gpad[ch0 * GPITCH + h0];

        // Sliding window of 16 duplicated g values: P[i] = (g[hb+i], g[hb+i])
        u64 P[16];
        {
            float4 a0 = *(const float4*)(gp);
            float4 a1 = *(const float4*)(gp + 4);
            float4 a2 = *(const float4*)(gp + 8);
            float4 a3 = *(const float4*)(gp + 12);
            P[0]  = pk2(a0.x, a0.x); P[1]  = pk2(a0.y, a0.y);
            P[2]  = pk2(a0.z, a0.z); P[3]  = pk2(a0.w, a0.w);
            P[4]  = pk2(a1.x, a1.x); P[5]  = pk2(a1.y, a1.y);
            P[6]  = pk2(a1.z, a1.z); P[7]  = pk2(a1.w, a1.w);
            P[8]  = pk2(a2.x, a2.x); P[9]  = pk2(a2.y, a2.y);
            P[10] = pk2(a2.z, a2.z); P[11] = pk2(a2.w, a2.w);
            P[12] = pk2(a3.x, a3.x); P[13] = pk2(a3.y, a3.y);
            P[14] = pk2(a3.z, a3.z); P[15] = pk2(a3.w, a3.w);
        }

        float* op = out + (size_t)h0 * CTOT + c0;
#pragma unroll
        for (int hb = 0; hb < HTILE; hb += 8) {
#pragma unroll
            for (int u = 0; u < 8; u++) {
                u64 acc = 0ull;
#pragma unroll
                for (int a = 0; a < 8; a++) acc = fma2(P[u + a], Wp[a], acc);
                *(u64*)op = acc;          // (out[h][c0], out[h][c0+1]) — 8B aligned
                op += CTOT;
            }
            if (hb < HTILE - 8) {
                float4 m0 = *(const float4*)(gp + hb + 16);
                float4 m1 = *(const float4*)(gp + hb + 20);
#pragma unroll
                for (int i = 0; i < 8; i++) P[i] = P[i + 8];
                P[8]  = pk2(m0.x, m0.x); P[9]  = pk2(m0.y, m0.y);
                P[10] = pk2(m0.z, m0.z); P[11] = pk2(m0.w, m0.w);
                P[12] = pk2(m1.x, m1.x); P[13] = pk2(m1.y, m1.y);
                P[14] = pk2(m1.z, m1.z); P[15] = pk2(m1.w, m1.w);
            }
        }
    } else {
        // Slow path: channel-crossing pairs (4 of 2048) and the 1-row tail tile.
        int kk0 = (c0 == CTOT - 1) ? 585 : c0 % 585;
        int kk1 = (c1 == CTOT - 1) ? 585 : c1 % 585;
        int hEnd = min(h0 + HTILE, HP);
        for (int h = h0; h < hEnd; h++) {
            const float* ga = &g_Gpad[ch0 * GPITCH + h];
            const float* gb = &g_Gpad[ch1 * GPITCH + h];
            float s0 = 0.f, s1 = 0.f;
#pragma unroll
            for (int a = 0; a < 8; a++) {
                s0 = fmaf(ga[a], g_Wmid[kk0 * 8 + a], s0);
                s1 = fmaf(gb[a], g_Wmid[kk1 * 8 + a], s1);
            }
            float2 o; o.x = s0; o.y = s1;
            *(float2*)&out[(size_t)h * CTOT + c0] = o;
        }
    }
}

extern "C" void kernel_launch(void* const* d_in, const int* in_sizes, int n_in,
                              void* d_out, int out_size) {
    const float* x       = (const float*)d_in[0];
    const float* kernels = (const float*)d_in[1];
    if (n_in >= 2 && in_sizes[0] == NK * 24) {   // defensive: swapped order
        kernels = (const float*)d_in[0];
        x       = (const float*)d_in[1];
    }
    float* out = (float*)d_out;

    prep<<<(CIN * GPITCH + 255) / 256, 256>>>(x, kernels);

    dim3 grid(NCP / 256, (HP + HTILE - 1) / HTILE);  // (8, 385)
    conv_main<<<grid, 256>>>(out);
}